// round 6
// baseline (speedup 1.0000x reference)
#include <cuda_runtime.h>
#include <stdint.h>
#include <math.h>

#define BATCH   2
#define SEQ     2048
#define DMODEL  1024
#define NHEAD   16
#define DK      64
#define MTOT    (BATCH*SEQ)
#define OUT_OFF ((size_t)MTOT*DMODEL)

// Scratch
__device__ float g_qc[MTOT*DMODEL];      // tf32-rounded inputs
__device__ float g_kc[MTOT*DMODEL];
__device__ float g_vc[MTOT*DMODEL];
__device__ float g_wqc[DMODEL*DMODEL];   // tf32-rounded weights (wq scaled by 0.125)
__device__ float g_wkc[DMODEL*DMODEL];
__device__ float g_wvc[DMODEL*DMODEL];
__device__ float g_woc[DMODEL*DMODEL];
__device__ float g_qp[MTOT*DMODEL];      // projections (stored tf32-rounded)
__device__ float g_kp[MTOT*DMODEL];
__device__ float g_vp[MTOT*DMODEL];
__device__ float g_ao[MTOT*DMODEL];      // PV out (stored tf32-rounded)

// ---------------------------------------------------------------------------
__device__ __forceinline__ uint32_t f2tf32(float x) {
    uint32_t u;
    asm("cvt.rna.tf32.f32 %0, %1;" : "=r"(u) : "f"(x));
    return u;
}

__device__ __forceinline__ void mma_tf32(float* d, const uint32_t* a, const uint32_t* b) {
    asm volatile(
        "mma.sync.aligned.m16n8k8.row.col.f32.tf32.tf32.f32 "
        "{%0,%1,%2,%3}, {%4,%5,%6,%7}, {%8,%9}, {%0,%1,%2,%3};"
        : "+f"(d[0]), "+f"(d[1]), "+f"(d[2]), "+f"(d[3])
        : "r"(a[0]), "r"(a[1]), "r"(a[2]), "r"(a[3]), "r"(b[0]), "r"(b[1]));
}

__device__ __forceinline__ void cp16(uint32_t saddr, const void* gptr) {
    asm volatile("cp.async.cg.shared.global [%0], [%1], 16;" :: "r"(saddr), "l"(gptr));
}
__device__ __forceinline__ void cp_commit() { asm volatile("cp.async.commit_group;"); }
__device__ __forceinline__ void cp_wait1()  { asm volatile("cp.async.wait_group 1;"); }
__device__ __forceinline__ void cp_wait0()  { asm volatile("cp.async.wait_group 0;"); }

// ---------------------------------------------------------------------------
// Elementwise tf32 pre-convert (with optional scale folded in)
// ---------------------------------------------------------------------------
__global__ __launch_bounds__(256) void cvt_kernel(
    const float4* __restrict__ src, float4* __restrict__ dst, int n4, float scale)
{
    int i = blockIdx.x * blockDim.x + threadIdx.x;
    if (i < n4) {
        float4 v = src[i];
        float4 r;
        r.x = __uint_as_float(f2tf32(v.x * scale));
        r.y = __uint_as_float(f2tf32(v.y * scale));
        r.z = __uint_as_float(f2tf32(v.z * scale));
        r.w = __uint_as_float(f2tf32(v.w * scale));
        dst[i] = r;
    }
}

// ---------------------------------------------------------------------------
// NT core: C[128x128] = A @ B^T, operands already tf32-rounded (no in-loop cvt).
// BK=16, 3-stage cp.async. CVTO: round output to tf32 at store.
// ---------------------------------------------------------------------------
template<bool CVTO>
__device__ __forceinline__ void gemm_nt_core(
    const float* __restrict__ A, const float* __restrict__ B, float* __restrict__ C,
    int K, int lda, int ldb, int ldc,
    int mBase, int nBase, float* dsm)
{
    const int tid  = threadIdx.x;
    const int lane = tid & 31;
    const int warp = tid >> 5;
    const int wm   = warp >> 2;
    const int wn   = warp & 3;
    const int q    = lane & 3;
    const int lr   = lane >> 2;
    const int r0   = tid >> 2;
    const int c4   = (tid & 3) << 2;

    const uint32_t sbase = (uint32_t)__cvta_generic_to_shared(dsm);
    const float* Ag = A + (size_t)mBase * lda;
    const float* Bg = B + (size_t)nBase * ldb;

    float acc[4][4][4];
    #pragma unroll
    for (int i = 0; i < 4; i++)
        #pragma unroll
        for (int j = 0; j < 4; j++)
            #pragma unroll
            for (int t = 0; t < 4; t++) acc[i][j][t] = 0.f;

    const int nc = K >> 4;

    #define NT_ISSUE(st, k0) do {                                              \
        uint32_t ab = sbase + (st) * 20480u + (uint32_t)(r0 * 80 + c4 * 4);    \
        uint32_t bb = ab + 10240u;                                             \
        cp16(ab,          Ag + (size_t)r0 * lda + (k0) + c4);                  \
        cp16(ab + 5120u,  Ag + (size_t)(r0 + 64) * lda + (k0) + c4);           \
        cp16(bb,          Bg + (size_t)r0 * ldb + (k0) + c4);                  \
        cp16(bb + 5120u,  Bg + (size_t)(r0 + 64) * ldb + (k0) + c4);           \
        cp_commit();                                                           \
    } while (0)

    NT_ISSUE(0, 0);
    if (nc > 1) NT_ISSUE(1, 16);

    for (int ch = 0; ch < nc; ch++) {
        if (ch + 1 < nc) cp_wait1(); else cp_wait0();
        __syncthreads();

        const float* As_ = dsm + (ch % 3) * 5120;
        const float* Bs_ = As_ + 2560;

        #pragma unroll
        for (int ks = 0; ks < 2; ks++) {
            const int kb = ks * 8 + q;
            uint32_t af[4][4], bf[4][2];
            #pragma unroll
            for (int mi = 0; mi < 4; mi++) {
                const int m0 = wm * 64 + mi * 16 + lr;
                af[mi][0] = __float_as_uint(As_[m0 * 20 + kb]);
                af[mi][1] = __float_as_uint(As_[(m0 + 8) * 20 + kb]);
                af[mi][2] = __float_as_uint(As_[m0 * 20 + kb + 4]);
                af[mi][3] = __float_as_uint(As_[(m0 + 8) * 20 + kb + 4]);
            }
            #pragma unroll
            for (int ni = 0; ni < 4; ni++) {
                const int n0 = wn * 32 + ni * 8 + lr;
                bf[ni][0] = __float_as_uint(Bs_[n0 * 20 + kb]);
                bf[ni][1] = __float_as_uint(Bs_[n0 * 20 + kb + 4]);
            }
            #pragma unroll
            for (int mi = 0; mi < 4; mi++)
                #pragma unroll
                for (int ni = 0; ni < 4; ni++)
                    mma_tf32(acc[mi][ni], af[mi], bf[ni]);
        }
        __syncthreads();
        if (ch + 2 < nc) NT_ISSUE((ch + 2) % 3, (ch + 2) * 16);
    }
    #undef NT_ISSUE

    // staged epilogue: two 64x128 halves through smem
    float* stg = dsm;
    #pragma unroll
    for (int half = 0; half < 2; half++) {
        if (wm == half) {
            #pragma unroll
            for (int mi = 0; mi < 4; mi++) {
                const int rr = mi * 16 + lr;
                #pragma unroll
                for (int ni = 0; ni < 4; ni++) {
                    const int cc = wn * 32 + ni * 8 + q * 2;
                    float v0 = acc[mi][ni][0], v1 = acc[mi][ni][1];
                    float v2 = acc[mi][ni][2], v3 = acc[mi][ni][3];
                    if (CVTO) {
                        v0 = __uint_as_float(f2tf32(v0));
                        v1 = __uint_as_float(f2tf32(v1));
                        v2 = __uint_as_float(f2tf32(v2));
                        v3 = __uint_as_float(f2tf32(v3));
                    }
                    stg[rr * 132 + cc]           = v0;
                    stg[rr * 132 + cc + 1]       = v1;
                    stg[(rr + 8) * 132 + cc]     = v2;
                    stg[(rr + 8) * 132 + cc + 1] = v3;
                }
            }
        }
        __syncthreads();
        #pragma unroll
        for (int i = 0; i < 8; i++) {
            const int row = (tid >> 5) * 8 + i;
            const int col = (tid & 31) * 4;
            *(float4*)&C[(size_t)(mBase + half * 64 + row) * ldc + nBase + col] =
                *(const float4*)&stg[row * 132 + col];
        }
        __syncthreads();
    }
}

// ---------------------------------------------------------------------------
__global__ __launch_bounds__(256, 2) void qkv_proj_kernel(
    const float* __restrict__ qc, const float* __restrict__ kc, const float* __restrict__ vc,
    const float* __restrict__ wq, const float* __restrict__ wk, const float* __restrict__ wv,
    float* __restrict__ qp, float* __restrict__ kp, float* __restrict__ vp)
{
    extern __shared__ float dsm[];
    const float* A; const float* B; float* C;
    if (blockIdx.z == 0)      { A = qc; B = wq; C = qp; }
    else if (blockIdx.z == 1) { A = kc; B = wk; C = kp; }
    else                      { A = vc; B = wv; C = vp; }
    gemm_nt_core<true>(A, B, C, DMODEL, DMODEL, DMODEL, DMODEL,
                       blockIdx.y * 128, blockIdx.x * 128, dsm);
}

__global__ __launch_bounds__(256, 2) void out_proj_kernel(
    const float* __restrict__ A, const float* __restrict__ B, float* __restrict__ C)
{
    extern __shared__ float dsm[];
    gemm_nt_core<false>(A, B, C, DMODEL, DMODEL, DMODEL, DMODEL,
                        blockIdx.y * 128, blockIdx.x * 128, dsm);
}

__global__ __launch_bounds__(256, 2) void scores_kernel(
    const float* __restrict__ qp, const float* __restrict__ kp, float* __restrict__ wts)
{
    extern __shared__ float dsm[];
    const int bh = blockIdx.z;
    const int b = bh >> 4, h = bh & 15;
    const float* A = qp + (size_t)b * SEQ * DMODEL + h * DK;
    const float* B = kp + (size_t)b * SEQ * DMODEL + h * DK;
    float*       C = wts + (size_t)bh * SEQ * SEQ;
    gemm_nt_core<false>(A, B, C, DK, DMODEL, DMODEL, SEQ,
                        blockIdx.y * 128, blockIdx.x * 128, dsm);
}

// ---------------------------------------------------------------------------
// Row softmax, in place, float4 path: 65536 rows of 2048.
// ---------------------------------------------------------------------------
__global__ __launch_bounds__(256) void softmax_kernel(float* __restrict__ Wt)
{
    float4* row4 = (float4*)(Wt + (size_t)blockIdx.x * SEQ);
    const int tid = threadIdx.x;
    __shared__ float red[8];

    float4 a = row4[tid];
    float4 b = row4[tid + 256];

    float m = fmaxf(fmaxf(fmaxf(a.x, a.y), fmaxf(a.z, a.w)),
                    fmaxf(fmaxf(b.x, b.y), fmaxf(b.z, b.w)));
    #pragma unroll
    for (int o = 16; o; o >>= 1) m = fmaxf(m, __shfl_xor_sync(0xFFFFFFFFu, m, o));
    if ((tid & 31) == 0) red[tid >> 5] = m;
    __syncthreads();
    m = red[0];
    #pragma unroll
    for (int i = 1; i < 8; i++) m = fmaxf(m, red[i]);
    __syncthreads();

    a.x = __expf(a.x - m); a.y = __expf(a.y - m);
    a.z = __expf(a.z - m); a.w = __expf(a.w - m);
    b.x = __expf(b.x - m); b.y = __expf(b.y - m);
    b.z = __expf(b.z - m); b.w = __expf(b.w - m);

    float s = a.x + a.y + a.z + a.w + b.x + b.y + b.z + b.w;
    #pragma unroll
    for (int o = 16; o; o >>= 1) s += __shfl_xor_sync(0xFFFFFFFFu, s, o);
    if ((tid & 31) == 0) red[tid >> 5] = s;
    __syncthreads();
    s = red[0];
    #pragma unroll
    for (int i = 1; i < 8; i++) s += red[i];
    const float inv = 1.f / s;

    a.x *= inv; a.y *= inv; a.z *= inv; a.w *= inv;
    b.x *= inv; b.y *= inv; b.z *= inv; b.w *= inv;
    row4[tid]       = a;
    row4[tid + 256] = b;
}

// ---------------------------------------------------------------------------
// PV: C[128,64] tiles = P @ V. 3-stage cp.async. P needs cvt (fp32 softmax
// values); V pre-rounded. Output stored tf32-rounded (feeds out-proj only).
// ---------------------------------------------------------------------------
__global__ __launch_bounds__(256, 2) void pv_async_kernel(
    const float* __restrict__ P, const float* __restrict__ V, float* __restrict__ C)
{
    __shared__ float sm[3 * 3712];

    const int z = blockIdx.z;
    const int b = z >> 4, h = z & 15;
    const int mBase = blockIdx.y * 128;

    const float* Ag = P + (size_t)z * SEQ * SEQ + (size_t)mBase * SEQ;
    const float* Bg = V + (size_t)b * SEQ * DMODEL + h * DK;
    float*       Cg = C + (size_t)b * SEQ * DMODEL + h * DK + (size_t)mBase * DMODEL;

    const int tid  = threadIdx.x;
    const int lane = tid & 31;
    const int warp = tid >> 5;
    const int wm   = warp >> 1;
    const int wn   = warp & 1;
    const int q    = lane & 3;
    const int lr   = lane >> 2;
    const int r0   = tid >> 2;
    const int c4   = (tid & 3) << 2;
    const int kr   = tid >> 4;
    const int n4   = (tid & 15) << 2;

    const uint32_t sbase = (uint32_t)__cvta_generic_to_shared(sm);

    float acc[2][4][4];
    #pragma unroll
    for (int i = 0; i < 2; i++)
        #pragma unroll
        for (int j = 0; j < 4; j++)
            #pragma unroll
            for (int t = 0; t < 4; t++) acc[i][j][t] = 0.f;

    #define PV_ISSUE(st, k0) do {                                               \
        uint32_t ab = sbase + (st) * 14848u + (uint32_t)(r0 * 80 + c4 * 4);     \
        uint32_t bb = sbase + (st) * 14848u + 10240u + (uint32_t)(kr * 288 + n4 * 4); \
        cp16(ab,         Ag + (size_t)r0 * SEQ + (k0) + c4);                    \
        cp16(ab + 5120u, Ag + (size_t)(r0 + 64) * SEQ + (k0) + c4);             \
        cp16(bb,         Bg + (size_t)((k0) + kr) * DMODEL + n4);               \
        cp_commit();                                                            \
    } while (0)

    const int nc = SEQ >> 4;
    PV_ISSUE(0, 0);
    PV_ISSUE(1, 16);

    for (int ch = 0; ch < nc; ch++) {
        if (ch + 1 < nc) cp_wait1(); else cp_wait0();
        __syncthreads();

        const float* As_ = sm + (ch % 3) * 3712;
        const float* Bs_ = As_ + 2560;

        #pragma unroll
        for (int ks = 0; ks < 2; ks++) {
            const int kb = ks * 8 + q;
            uint32_t af[2][4], bf[4][2];
            #pragma unroll
            for (int mi = 0; mi < 2; mi++) {
                const int m0 = wm * 32 + mi * 16 + lr;
                af[mi][0] = f2tf32(As_[m0 * 20 + kb]);
                af[mi][1] = f2tf32(As_[(m0 + 8) * 20 + kb]);
                af[mi][2] = f2tf32(As_[m0 * 20 + kb + 4]);
                af[mi][3] = f2tf32(As_[(m0 + 8) * 20 + kb + 4]);
            }
            #pragma unroll
            for (int ni = 0; ni < 4; ni++) {
                const int n0 = wn * 32 + ni * 8 + lr;
                bf[ni][0] = __float_as_uint(Bs_[kb * 72 + n0]);
                bf[ni][1] = __float_as_uint(Bs_[(kb + 4) * 72 + n0]);
            }
            #pragma unroll
            for (int mi = 0; mi < 2; mi++)
                #pragma unroll
                for (int ni = 0; ni < 4; ni++)
                    mma_tf32(acc[mi][ni], af[mi], bf[ni]);
        }
        __syncthreads();
        if (ch + 2 < nc) PV_ISSUE((ch + 2) % 3, (ch + 2) * 16);
    }
    #undef PV_ISSUE

    // staged epilogue (output tf32-rounded; consumed only by out-proj MMA)
    float* stg = sm;
    #pragma unroll
    for (int mi = 0; mi < 2; mi++) {
        const int rr = wm * 32 + mi * 16 + lr;
        #pragma unroll
        for (int ni = 0; ni < 4; ni++) {
            const int cc = wn * 32 + ni * 8 + q * 2;
            stg[rr * 68 + cc]           = __uint_as_float(f2tf32(acc[mi][ni][0]));
            stg[rr * 68 + cc + 1]       = __uint_as_float(f2tf32(acc[mi][ni][1]));
            stg[(rr + 8) * 68 + cc]     = __uint_as_float(f2tf32(acc[mi][ni][2]));
            stg[(rr + 8) * 68 + cc + 1] = __uint_as_float(f2tf32(acc[mi][ni][3]));
        }
    }
    __syncthreads();
    #pragma unroll
    for (int i = 0; i < 8; i++) {
        const int row = (tid >> 4) * 8 + i;
        const int col = (tid & 15) * 4;
        *(float4*)&Cg[(size_t)row * DMODEL + col] = *(const float4*)&stg[row * 68 + col];
    }
}

// ---------------------------------------------------------------------------
extern "C" void kernel_launch(void* const* d_in, const int* in_sizes, int n_in,
                              void* d_out, int out_size)
{
    const float* q  = (const float*)d_in[0];
    const float* k  = (const float*)d_in[1];
    const float* v  = (const float*)d_in[2];
    const float* Wq = (const float*)d_in[3];
    const float* Wk = (const float*)d_in[4];
    const float* Wv = (const float*)d_in[5];
    const float* Wo = (const float*)d_in[6];
    float* out = (float*)d_out;
    float* wts = out + OUT_OFF;

    float *qc, *kc, *vc, *wqc, *wkc, *wvc, *woc, *qp, *kp, *vp, *ao;
    cudaGetSymbolAddress((void**)&qc,  g_qc);
    cudaGetSymbolAddress((void**)&kc,  g_kc);
    cudaGetSymbolAddress((void**)&vc,  g_vc);
    cudaGetSymbolAddress((void**)&wqc, g_wqc);
    cudaGetSymbolAddress((void**)&wkc, g_wkc);
    cudaGetSymbolAddress((void**)&wvc, g_wvc);
    cudaGetSymbolAddress((void**)&woc, g_woc);
    cudaGetSymbolAddress((void**)&qp,  g_qp);
    cudaGetSymbolAddress((void**)&kp,  g_kp);
    cudaGetSymbolAddress((void**)&vp,  g_vp);
    cudaGetSymbolAddress((void**)&ao,  g_ao);

    const int DSM = 3 * 20480;
    cudaFuncSetAttribute(qkv_proj_kernel, cudaFuncAttributeMaxDynamicSharedMemorySize, DSM);
    cudaFuncSetAttribute(scores_kernel,  cudaFuncAttributeMaxDynamicSharedMemorySize, DSM);
    cudaFuncSetAttribute(out_proj_kernel, cudaFuncAttributeMaxDynamicSharedMemorySize, DSM);

    const dim3 thr(256);
    const int N_IN = MTOT * DMODEL / 4;     // 1048576 float4
    const int N_W  = DMODEL * DMODEL / 4;   // 262144 float4

    // tf32 pre-convert (0.125 score scale folded into Wq — exact power of 2)
    cvt_kernel<<<(N_IN + 255) / 256, 256>>>((const float4*)q,  (float4*)qc,  N_IN, 1.f);
    cvt_kernel<<<(N_IN + 255) / 256, 256>>>((const float4*)k,  (float4*)kc,  N_IN, 1.f);
    cvt_kernel<<<(N_IN + 255) / 256, 256>>>((const float4*)v,  (float4*)vc,  N_IN, 1.f);
    cvt_kernel<<<(N_W + 255) / 256, 256>>>((const float4*)Wq, (float4*)wqc, N_W, 0.125f);
    cvt_kernel<<<(N_W + 255) / 256, 256>>>((const float4*)Wk, (float4*)wkc, N_W, 1.f);
    cvt_kernel<<<(N_W + 255) / 256, 256>>>((const float4*)Wv, (float4*)wvc, N_W, 1.f);
    cvt_kernel<<<(N_W + 255) / 256, 256>>>((const float4*)Wo, (float4*)woc, N_W, 1.f);

    // Q/K/V projections (outputs stored tf32-rounded)
    qkv_proj_kernel<<<dim3(8, 32, 3), thr, DSM>>>(qc, kc, vc, wqc, wkc, wvc, qp, kp, vp);

    // Scores (scale already folded into qp)
    scores_kernel<<<dim3(16, 16, 32), thr, DSM>>>(qp, kp, wts);

    // Softmax in place
    softmax_kernel<<<BATCH * NHEAD * SEQ, 256>>>(wts);

    // P @ V
    pv_async_kernel<<<dim3(1, 16, 32), thr>>>(wts, vp, ao);

    // Output projection
    out_proj_kernel<<<dim3(8, 32, 1), thr, DSM>>>(ao, woc, out);
}